// round 16
// baseline (speedup 1.0000x reference)
#include <cuda_runtime.h>
#include <cuda_fp16.h>
#include <stdint.h>

#define H 128
#define MAX_ROWS 100000
#define BM 128
#define LDH 136          // smem row pitch in halfs (272B): conflict-free ldmatrix
#define PGRID 296        // persistent precompute CTAs (2 per SM)

// Precomputed tables in fp16: A = user@W1_top + b1, B = movie@W1_bot
__device__ __half g_A[(size_t)MAX_ROWS * H];
__device__ __half g_B[(size_t)MAX_ROWS * H];
// W1 converted to fp16 once per launch (top half then bottom half)
__device__ __half g_Wh[2 * H * H];

__device__ __forceinline__ uint32_t smem_u32(const void* p) {
    return (uint32_t)__cvta_generic_to_shared(p);
}
__device__ __forceinline__ void ldsm_x4(uint32_t& r0, uint32_t& r1,
                                        uint32_t& r2, uint32_t& r3, uint32_t addr) {
    asm volatile("ldmatrix.sync.aligned.m8n8.x4.shared.b16 {%0,%1,%2,%3}, [%4];"
                 : "=r"(r0), "=r"(r1), "=r"(r2), "=r"(r3) : "r"(addr));
}
__device__ __forceinline__ void ldsm_x4_t(uint32_t& r0, uint32_t& r1,
                                          uint32_t& r2, uint32_t& r3, uint32_t addr) {
    asm volatile("ldmatrix.sync.aligned.m8n8.x4.trans.shared.b16 {%0,%1,%2,%3}, [%4];"
                 : "=r"(r0), "=r"(r1), "=r"(r2), "=r"(r3) : "r"(addr));
}
__device__ __forceinline__ void mma16816(float& c0, float& c1, float& c2, float& c3,
                                         uint32_t a0, uint32_t a1, uint32_t a2, uint32_t a3,
                                         uint32_t b0, uint32_t b1) {
    asm volatile("mma.sync.aligned.m16n8k16.row.col.f32.f16.f16.f32 "
                 "{%0,%1,%2,%3}, {%4,%5,%6,%7}, {%8,%9}, {%0,%1,%2,%3};"
                 : "+f"(c0), "+f"(c1), "+f"(c2), "+f"(c3)
                 : "r"(a0), "r"(a1), "r"(a2), "r"(a3), "r"(b0), "r"(b1));
}
__device__ __forceinline__ uint32_t pack_h2(float x, float y) {
    __half2 h = __floats2half2_rn(x, y);
    return *(uint32_t*)&h;
}

// ---------------------------------------------------------------------------
// Prologue: convert W1 (2*H*H fp32) -> g_Wh (fp16), fires PDL trigger.
// ---------------------------------------------------------------------------
__global__ void convert_W_kernel(const float* __restrict__ W1)
{
    int i = blockIdx.x * blockDim.x + threadIdx.x;
    float4 v = ((const float4*)W1)[i];
    uint2 u;
    u.x = pack_h2(v.x, v.y);
    u.y = pack_h2(v.z, v.w);
    ((uint2*)g_Wh)[i] = u;
    cudaTriggerProgrammaticLaunchCompletion();
}

// ---------------------------------------------------------------------------
// Persistent fused precompute (fp16 MMA), cross-tile double-buffered X.
// 296 CTAs, tile T = blockIdx.x + k*gridDim.x over blocksA+blocksB tiles.
// While computing tile t from Xb[p], each thread stages tile t+1 into
// Xb[p^1] in 2-float4 chunks interleaved with the 8 k-block MMA iterations.
// W staged once (re-staged once at the A->B boundary crossing).
// ---------------------------------------------------------------------------
__global__ __launch_bounds__(256, 2)
void precompute_fp16(const float* __restrict__ user,
                     const float* __restrict__ movie,
                     const float* __restrict__ b1,
                     int n_users, int n_movies, int blocksA, int n_tiles)
{
    extern __shared__ __half sm[];
    __half* Xb0 = sm;                       // [BM][LDH]
    __half* Xb1 = sm + BM * LDH;            // [BM][LDH]
    __half* Ws  = sm + 2 * BM * LDH;        // [H][LDH]

    const int tid = threadIdx.x;
    const int rb  = tid >> 5;               // staging base row 0..7
    const int c4  = tid & 31;               // float4 column

    int T = blockIdx.x;
    if (T >= n_tiles) return;

    bool isA = T < blocksA;
    int  row0 = (isA ? T : T - blocksA) * BM;
    const float* X = isA ? user : movie;
    int  nr = isA ? n_users : n_movies;

    // Stage X(first tile) into Xb0 BEFORE gridsync (independent of g_Wh).
    #pragma unroll
    for (int i = 0; i < 16; i++) {
        int r = rb + 8 * i;
        float4 v = make_float4(0.f, 0.f, 0.f, 0.f);
        if (row0 + r < nr)
            v = ((const float4*)X)[(size_t)(row0 + r) * 32 + c4];
        *(uint2*)&Xb0[r * LDH + (c4 << 2)] =
            make_uint2(pack_h2(v.x, v.y), pack_h2(v.z, v.w));
    }

    cudaGridDependencySynchronize();

    const __half* curWh = isA ? g_Wh : (g_Wh + H * H);
    #pragma unroll
    for (int i = 0; i < 8; i++) {
        int idx = tid + i * 256;
        uint4 v = ((const uint4*)curWh)[idx];
        *(uint4*)&Ws[(idx >> 4) * LDH + ((idx & 15) << 3)] = v;
    }
    __syncthreads();

    const int warp = tid >> 5;
    const int lane = tid & 31;
    const int wrow = warp << 4;
    const int g    = lane >> 2;
    const int t    = lane & 3;
    const uint32_t b_base = smem_u32(Ws) +
        ((((lane & 15)) * LDH + ((lane >> 4) << 3)) << 1);
    const uint32_t a_off =
        (((wrow + (lane & 15)) * LDH + ((lane >> 4) << 3)) << 1);

    int p = 0;
    const int stride = gridDim.x;

    for (;;) {
        __half* Xc = p ? Xb1 : Xb0;
        __half* Xn = p ? Xb0 : Xb1;
        const uint32_t a_base = smem_u32(Xc) + a_off;
        __half* outp = isA ? g_A : g_B;
        const float* bias = isA ? b1 : nullptr;

        // Next-tile parameters
        int  Tn = T + stride;
        bool has_next = Tn < n_tiles;
        bool nIsA = Tn < blocksA;
        int  nrow0 = (nIsA ? Tn : Tn - blocksA) * BM;
        const float* nX = nIsA ? user : movie;
        int  nnr = nIsA ? n_users : n_movies;

        float acc[16][4];
        #pragma unroll
        for (int n = 0; n < 16; n++)
            acc[n][0] = acc[n][1] = acc[n][2] = acc[n][3] = 0.f;

        if (has_next) {
            // Pipelined mainloop: stage 2 chunks of next tile per k-block.
            float4 pf0, pf1;
            {
                int r0n = nrow0 + rb;
                int r1n = r0n + 8;
                pf0 = (r0n < nnr) ? ((const float4*)nX)[(size_t)r0n * 32 + c4]
                                  : make_float4(0.f, 0.f, 0.f, 0.f);
                pf1 = (r1n < nnr) ? ((const float4*)nX)[(size_t)r1n * 32 + c4]
                                  : make_float4(0.f, 0.f, 0.f, 0.f);
            }
            #pragma unroll
            for (int kb8 = 0; kb8 < 8; kb8++) {
                float4 s0 = pf0, s1 = pf1;
                if (kb8 < 7) {
                    int ra = nrow0 + rb + 8 * (2 * kb8 + 2);
                    int rc = ra + 8;
                    pf0 = (ra < nnr) ? ((const float4*)nX)[(size_t)ra * 32 + c4]
                                     : make_float4(0.f, 0.f, 0.f, 0.f);
                    pf1 = (rc < nnr) ? ((const float4*)nX)[(size_t)rc * 32 + c4]
                                     : make_float4(0.f, 0.f, 0.f, 0.f);
                }
                {
                    int rr0 = rb + 8 * (2 * kb8);
                    int rr1 = rr0 + 8;
                    *(uint2*)&Xn[rr0 * LDH + (c4 << 2)] =
                        make_uint2(pack_h2(s0.x, s0.y), pack_h2(s0.z, s0.w));
                    *(uint2*)&Xn[rr1 * LDH + (c4 << 2)] =
                        make_uint2(pack_h2(s1.x, s1.y), pack_h2(s1.z, s1.w));
                }

                const int kb = kb8 << 4;
                uint32_t a0, a1, a2, a3;
                ldsm_x4(a0, a1, a2, a3, a_base + (kb << 1));
                uint32_t b[8][4];
                #pragma unroll
                for (int np = 0; np < 8; np++)
                    ldsm_x4_t(b[np][0], b[np][1], b[np][2], b[np][3],
                              b_base + ((kb * LDH + (np << 4)) << 1));
                #pragma unroll
                for (int np = 0; np < 8; np++) {
                    mma16816(acc[2*np][0], acc[2*np][1], acc[2*np][2], acc[2*np][3],
                             a0, a1, a2, a3, b[np][0], b[np][1]);
                    mma16816(acc[2*np+1][0], acc[2*np+1][1], acc[2*np+1][2], acc[2*np+1][3],
                             a0, a1, a2, a3, b[np][2], b[np][3]);
                }
            }
        } else {
            // Last tile: plain mainloop.
            #pragma unroll
            for (int kb8 = 0; kb8 < 8; kb8++) {
                const int kb = kb8 << 4;
                uint32_t a0, a1, a2, a3;
                ldsm_x4(a0, a1, a2, a3, a_base + (kb << 1));
                uint32_t b[8][4];
                #pragma unroll
                for (int np = 0; np < 8; np++)
                    ldsm_x4_t(b[np][0], b[np][1], b[np][2], b[np][3],
                              b_base + ((kb * LDH + (np << 4)) << 1));
                #pragma unroll
                for (int np = 0; np < 8; np++) {
                    mma16816(acc[2*np][0], acc[2*np][1], acc[2*np][2], acc[2*np][3],
                             a0, a1, a2, a3, b[np][0], b[np][1]);
                    mma16816(acc[2*np+1][0], acc[2*np+1][1], acc[2*np+1][2], acc[2*np+1][3],
                             a0, a1, a2, a3, b[np][2], b[np][3]);
                }
            }
        }

        // Epilogue: acc (bias added, fp16) -> Xc own rows (conflict-free),
        // barrier, coalesced copy-out.
        #pragma unroll
        for (int nt = 0; nt < 16; nt++) {
            const int col = (nt << 3) + (t << 1);
            float bxv = 0.f, byv = 0.f;
            if (bias) { bxv = bias[col]; byv = bias[col + 1]; }
            *(uint32_t*)&Xc[(wrow + g) * LDH + col] =
                pack_h2(acc[nt][0] + bxv, acc[nt][1] + byv);
            *(uint32_t*)&Xc[(wrow + g + 8) * LDH + col] =
                pack_h2(acc[nt][2] + bxv, acc[nt][3] + byv);
        }
        __syncthreads();   // epilogue STS visible; next-X staging complete

        #pragma unroll
        for (int i = 0; i < 8; i++) {
            int idx = tid + i * 256;
            int r = idx >> 4;
            int c = (idx & 15) << 3;
            if (row0 + r < nr) {
                uint4 v = *(const uint4*)&Xc[r * LDH + c];
                *(uint4*)&outp[(size_t)(row0 + r) * H + c] = v;
            }
        }

        if (!has_next) break;
        __syncthreads();   // Xc free for reuse as the next staging target

        // Advance to next tile
        T = Tn; isA = nIsA; row0 = nrow0; X = nX; nr = nnr; p ^= 1;
        const __half* newWh = isA ? g_Wh : (g_Wh + H * H);
        if (newWh != curWh) {
            curWh = newWh;
            #pragma unroll
            for (int i = 0; i < 8; i++) {
                int idx = tid + i * 256;
                uint4 v = ((const uint4*)curWh)[idx];
                *(uint4*)&Ws[(idx >> 4) * LDH + ((idx & 15) << 3)] = v;
            }
            __syncthreads();
        }
    }

    cudaTriggerProgrammaticLaunchCompletion();
}

// ---------------------------------------------------------------------------
// Edge phase (R5-proven layout, LTS-capped ~41.6us at 512B/edge):
// out[e] = relu(A[src[e]] + B[dst[e]]) . W2 + b2
// ---------------------------------------------------------------------------
__device__ __forceinline__ float dot8(uint4 ua, uint4 ub,
                                      __half2 w0, __half2 w1,
                                      __half2 w2, __half2 w3, __half2 hz) {
    __half2 h0 = __hmax2(__hadd2(*(__half2*)&ua.x, *(__half2*)&ub.x), hz);
    __half2 h1 = __hmax2(__hadd2(*(__half2*)&ua.y, *(__half2*)&ub.y), hz);
    __half2 h2 = __hmax2(__hadd2(*(__half2*)&ua.z, *(__half2*)&ub.z), hz);
    __half2 h3 = __hmax2(__hadd2(*(__half2*)&ua.w, *(__half2*)&ub.w), hz);
    __half2 c1 = __hfma2(h1, w1, __hmul2(h0, w0));
    __half2 c2 = __hfma2(h3, w3, __hmul2(h2, w2));
    float2 f1 = __half22float2(c1);
    float2 f2 = __half22float2(c2);
    return (f1.x + f1.y) + (f2.x + f2.y);
}

__global__ __launch_bounds__(256)
void edge_kernel(const int* __restrict__ ei,
                 const float* __restrict__ W2,
                 const float* __restrict__ b2,
                 float* __restrict__ out,
                 int E)
{
    const int lane = threadIdx.x & 31;
    const int half = lane >> 4;
    const int q    = lane & 15;
    const int gw   = (blockIdx.x * blockDim.x + threadIdx.x) >> 5;
    const int nw   = (gridDim.x * blockDim.x) >> 5;

    // Prologue reads only harness inputs — safe before gridsync.
    float4 wlo = *(const float4*)&W2[q * 8];
    float4 whi = *(const float4*)&W2[q * 8 + 4];
    const __half2 w0 = __floats2half2_rn(wlo.x, wlo.y);
    const __half2 w1 = __floats2half2_rn(wlo.z, wlo.w);
    const __half2 w2 = __floats2half2_rn(whi.x, whi.y);
    const __half2 w3 = __floats2half2_rn(whi.z, whi.w);
    const float b2v = b2[0];
    const __half2 hz = __float2half2_rn(0.f);

    cudaGridDependencySynchronize();

    if ((E & 3) == 0) {
        for (int e0 = gw * 4; e0 < E; e0 += nw * 4) {
            int4 sq = *(const int4*)&ei[e0];
            int4 dq = *(const int4*)&ei[E + e0];
            int sA = half ? sq.y : sq.x;
            int dA = half ? dq.y : dq.x;
            int sB = half ? sq.w : sq.z;
            int dB = half ? dq.w : dq.z;

            uint4 a0  = *(const uint4*)&g_A[((size_t)sA << 7) + (q << 3)];
            uint4 bb0 = *(const uint4*)&g_B[((size_t)dA << 7) + (q << 3)];
            uint4 a1  = *(const uint4*)&g_A[((size_t)sB << 7) + (q << 3)];
            uint4 bb1 = *(const uint4*)&g_B[((size_t)dB << 7) + (q << 3)];

            float v0 = dot8(a0, bb0, w0, w1, w2, w3, hz);
            float v1 = dot8(a1, bb1, w0, w1, w2, w3, hz);

            #pragma unroll
            for (int off = 8; off > 0; off >>= 1) {
                v0 += __shfl_xor_sync(0xFFFFFFFFu, v0, off);
                v1 += __shfl_xor_sync(0xFFFFFFFFu, v1, off);
            }
            if (q == 0) {
                out[e0 + half]     = v0 + b2v;
                out[e0 + 2 + half] = v1 + b2v;
            }
        }
    } else {
        for (int e = gw; e < E; e += nw) {
            int s = ei[e], d = ei[E + e];
            uint2 ua = *(const uint2*)&g_A[(size_t)s * H + lane * 4];
            uint2 ub = *(const uint2*)&g_B[(size_t)d * H + lane * 4];
            __half2 h0 = __hmax2(__hadd2(*(__half2*)&ua.x, *(__half2*)&ub.x), hz);
            __half2 h1 = __hmax2(__hadd2(*(__half2*)&ua.y, *(__half2*)&ub.y), hz);
            float2 f0 = __half22float2(h0);
            float2 f1 = __half22float2(h1);
            float4 wv = *(const float4*)&W2[lane * 4];
            float v = f0.x * wv.x + f0.y * wv.y + f1.x * wv.z + f1.y * wv.w;
            #pragma unroll
            for (int off = 16; off > 0; off >>= 1)
                v += __shfl_xor_sync(0xFFFFFFFFu, v, off);
            if (lane == 0) out[e] = v + b2v;
        }
    }
}

// ---------------------------------------------------------------------------
extern "C" void kernel_launch(void* const* d_in, const int* in_sizes, int n_in,
                              void* d_out, int out_size)
{
    const float* user  = (const float*)d_in[0];
    const float* movie = (const float*)d_in[1];
    const int*   ei    = (const int*)d_in[2];
    const float* W1    = (const float*)d_in[3];
    const float* b1    = (const float*)d_in[4];
    const float* W2    = (const float*)d_in[5];
    const float* b2    = (const float*)d_in[6];
    float* out = (float*)d_out;

    int n_users  = in_sizes[0] / H;
    int n_movies = in_sizes[1] / H;
    int E        = in_sizes[2] / 2;
    if (n_users  > MAX_ROWS) n_users  = MAX_ROWS;
    if (n_movies > MAX_ROWS) n_movies = MAX_ROWS;

    const int blocksA = (n_users  + BM - 1) / BM;
    const int blocksB = (n_movies + BM - 1) / BM;
    const int n_tiles = blocksA + blocksB;
    const int pgrid   = (n_tiles < PGRID) ? n_tiles : PGRID;

    const int smem_bytes = (2 * BM + H) * LDH * (int)sizeof(__half);  // 104,448
    static bool attr_set = false;
    if (!attr_set) {
        cudaFuncSetAttribute(precompute_fp16,
                             cudaFuncAttributeMaxDynamicSharedMemorySize,
                             smem_bytes);
        attr_set = true;
    }

    // 1) W1 -> fp16 (fires PDL trigger early)
    convert_W_kernel<<<32, 256>>>(W1);

    cudaLaunchAttribute pdl[1];
    pdl[0].id = cudaLaunchAttributeProgrammaticStreamSerialization;
    pdl[0].val.programmaticStreamSerializationAllowed = 1;

    // 2) Persistent precompute — PDL overlaps with convert.
    {
        cudaLaunchConfig_t cfg = {};
        cfg.gridDim = dim3((unsigned)pgrid, 1, 1);
        cfg.blockDim = dim3(256, 1, 1);
        cfg.dynamicSmemBytes = (size_t)smem_bytes;
        cfg.stream = 0;
        cfg.attrs = pdl;
        cfg.numAttrs = 1;
        cudaLaunchKernelEx(&cfg, precompute_fp16,
                           user, movie, b1, n_users, n_movies, blocksA, n_tiles);
    }
    // 3) Edge scoring — PDL ramps under precompute tail.
    {
        cudaLaunchConfig_t cfg = {};
        cfg.gridDim = dim3(148 * 8, 1, 1);
        cfg.blockDim = dim3(256, 1, 1);
        cfg.dynamicSmemBytes = 0;
        cfg.stream = 0;
        cfg.attrs = pdl;
        cfg.numAttrs = 1;
        cudaLaunchKernelEx(&cfg, edge_kernel, ei, W2, b2, out, E);
    }
}

// round 17
// speedup vs baseline: 1.1138x; 1.1138x over previous
#include <cuda_runtime.h>
#include <cuda_fp16.h>
#include <stdint.h>

#define H 128
#define MAX_ROWS 100000
#define BM 128
#define LDH 136          // smem row pitch in halfs (272B): conflict-free ldmatrix

// Precomputed tables in fp16: A = user@W1_top + b1, B = movie@W1_bot
__device__ __half g_A[(size_t)MAX_ROWS * H];
__device__ __half g_B[(size_t)MAX_ROWS * H];
// W1 converted to fp16 once per launch (top half then bottom half)
__device__ __half g_Wh[2 * H * H];

__device__ __forceinline__ uint32_t smem_u32(const void* p) {
    return (uint32_t)__cvta_generic_to_shared(p);
}
__device__ __forceinline__ void ldsm_x4(uint32_t& r0, uint32_t& r1,
                                        uint32_t& r2, uint32_t& r3, uint32_t addr) {
    asm volatile("ldmatrix.sync.aligned.m8n8.x4.shared.b16 {%0,%1,%2,%3}, [%4];"
                 : "=r"(r0), "=r"(r1), "=r"(r2), "=r"(r3) : "r"(addr));
}
__device__ __forceinline__ void ldsm_x4_t(uint32_t& r0, uint32_t& r1,
                                          uint32_t& r2, uint32_t& r3, uint32_t addr) {
    asm volatile("ldmatrix.sync.aligned.m8n8.x4.trans.shared.b16 {%0,%1,%2,%3}, [%4];"
                 : "=r"(r0), "=r"(r1), "=r"(r2), "=r"(r3) : "r"(addr));
}
__device__ __forceinline__ void mma16816(float& c0, float& c1, float& c2, float& c3,
                                         uint32_t a0, uint32_t a1, uint32_t a2, uint32_t a3,
                                         uint32_t b0, uint32_t b1) {
    asm volatile("mma.sync.aligned.m16n8k16.row.col.f32.f16.f16.f32 "
                 "{%0,%1,%2,%3}, {%4,%5,%6,%7}, {%8,%9}, {%0,%1,%2,%3};"
                 : "+f"(c0), "+f"(c1), "+f"(c2), "+f"(c3)
                 : "r"(a0), "r"(a1), "r"(a2), "r"(a3), "r"(b0), "r"(b1));
}
__device__ __forceinline__ uint32_t pack_h2(float x, float y) {
    __half2 h = __floats2half2_rn(x, y);
    return *(uint32_t*)&h;
}

// ---------------------------------------------------------------------------
// Prologue: convert W1 (2*H*H fp32) -> g_Wh (fp16), fires PDL trigger.
// ---------------------------------------------------------------------------
__global__ void convert_W_kernel(const float* __restrict__ W1)
{
    int i = blockIdx.x * blockDim.x + threadIdx.x;
    float4 v = ((const float4*)W1)[i];
    uint2 u;
    u.x = pack_h2(v.x, v.y);
    u.y = pack_h2(v.z, v.w);
    ((uint2*)g_Wh)[i] = u;
    cudaTriggerProgrammaticLaunchCompletion();
}

// ---------------------------------------------------------------------------
// Fused precompute (fp16 MMA): blocks [0, blocksA) -> A table, rest -> B.
// Load order: issue ALL 16 X LDG.128 into registers -> gridsync -> stage W
// (L2-hot) -> convert+STS X (DRAM latency now hidden) -> mainloop.
// Epilogue: acc -> smem (conflict-free STS.32) -> coalesced STG.128.
// ---------------------------------------------------------------------------
__global__ __launch_bounds__(256, 2)
void precompute_fp16(const float* __restrict__ user,
                     const float* __restrict__ movie,
                     const float* __restrict__ b1,
                     int n_users, int n_movies, int blocksA)
{
    const bool isA = (int)blockIdx.x < blocksA;
    const float* X    = isA ? user : movie;
    const __half* Wh  = isA ? g_Wh : (g_Wh + H * H);
    const float* bias = isA ? b1   : nullptr;
    __half* out       = isA ? g_A  : g_B;
    const int n_rows  = isA ? n_users : n_movies;
    const int bx      = isA ? (int)blockIdx.x : (int)blockIdx.x - blocksA;
    const int row0    = bx * BM;

    extern __shared__ __half sm[];
    __half* Xs = sm;               // [BM][LDH]
    __half* Ws = sm + BM * LDH;    // [H][LDH]

    const int tid = threadIdx.x;

    // --- Phase A: issue all 16 X LDG.128 into registers (acc not yet live) ---
    float4 xv[16];
    if (row0 + BM <= n_rows) {
        #pragma unroll
        for (int i = 0; i < 16; i++) {
            int idx = tid + i * 256;
            int r = idx >> 5;
            int c4 = idx & 31;
            xv[i] = ((const float4*)X)[(size_t)(row0 + r) * 32 + c4];
        }
    } else {
        #pragma unroll
        for (int i = 0; i < 16; i++) {
            int idx = tid + i * 256;
            int r = idx >> 5;
            int c4 = idx & 31;
            xv[i] = make_float4(0.f, 0.f, 0.f, 0.f);
            if (row0 + r < n_rows)
                xv[i] = ((const float4*)X)[(size_t)(row0 + r) * 32 + c4];
        }
    }

    // --- Phase B: wait for convert grid (overlaps X flight) ---
    cudaGridDependencySynchronize();

    // --- Phase C: stage W (fp16, L2-hot): 2048 uint4, 8 per thread ---
    #pragma unroll
    for (int i = 0; i < 8; i++) {
        int idx = tid + i * 256;
        uint4 v = ((const uint4*)Wh)[idx];
        int r = idx >> 4;
        int c = (idx & 15) << 3;
        *(uint4*)&Ws[r * LDH + c] = v;
    }

    // --- Phase D: convert + STS the X registers (DRAM latency absorbed) ---
    #pragma unroll
    for (int i = 0; i < 16; i++) {
        int idx = tid + i * 256;
        int r = idx >> 5;
        int c4 = idx & 31;
        uint32_t* p = (uint32_t*)&Xs[r * LDH + (c4 << 2)];
        p[0] = pack_h2(xv[i].x, xv[i].y);
        p[1] = pack_h2(xv[i].z, xv[i].w);
    }
    __syncthreads();

    const int warp = tid >> 5;
    const int lane = tid & 31;
    const int wrow = warp << 4;
    const int g    = lane >> 2;
    const int t    = lane & 3;

    const uint32_t a_base = smem_u32(Xs) +
        (((wrow + (lane & 15)) * LDH + ((lane >> 4) << 3)) << 1);
    const uint32_t b_base = smem_u32(Ws) +
        ((((lane & 15)) * LDH + ((lane >> 4) << 3)) << 1);

    float acc[16][4];
    #pragma unroll
    for (int n = 0; n < 16; n++)
        acc[n][0] = acc[n][1] = acc[n][2] = acc[n][3] = 0.f;

    #pragma unroll
    for (int kb8 = 0; kb8 < 8; kb8++) {
        const int kb = kb8 << 4;
        uint32_t a0, a1, a2, a3;
        ldsm_x4(a0, a1, a2, a3, a_base + (kb << 1));

        uint32_t b[8][4];
        #pragma unroll
        for (int np = 0; np < 8; np++)
            ldsm_x4_t(b[np][0], b[np][1], b[np][2], b[np][3],
                      b_base + ((kb * LDH + (np << 4)) << 1));

        #pragma unroll
        for (int np = 0; np < 8; np++) {
            mma16816(acc[2*np][0], acc[2*np][1], acc[2*np][2], acc[2*np][3],
                     a0, a1, a2, a3, b[np][0], b[np][1]);
            mma16816(acc[2*np+1][0], acc[2*np+1][1], acc[2*np+1][2], acc[2*np+1][3],
                     a0, a1, a2, a3, b[np][2], b[np][3]);
        }
    }

    // Epilogue: acc (bias added, fp16) -> Xs (warp-private rows; bank =
    // g*4+t+const mod 32, conflict-free), barrier, coalesced uint4 copy-out.
    #pragma unroll
    for (int nt = 0; nt < 16; nt++) {
        const int col = (nt << 3) + (t << 1);
        float bxv = 0.f, byv = 0.f;
        if (bias) { bxv = bias[col]; byv = bias[col + 1]; }
        *(uint32_t*)&Xs[(wrow + g) * LDH + col] =
            pack_h2(acc[nt][0] + bxv, acc[nt][1] + byv);
        *(uint32_t*)&Xs[(wrow + g + 8) * LDH + col] =
            pack_h2(acc[nt][2] + bxv, acc[nt][3] + byv);
    }
    __syncthreads();

    // Coalesced copy-out: 2048 uint4, 8 per thread, STG.128.
    #pragma unroll
    for (int i = 0; i < 8; i++) {
        int idx = tid + i * 256;
        int r = idx >> 4;              // 16 uint4 per 128-half row
        int c = (idx & 15) << 3;
        if (row0 + r < n_rows) {
            uint4 v = *(const uint4*)&Xs[r * LDH + c];
            *(uint4*)&out[(size_t)(row0 + r) * H + c] = v;
        }
    }

    cudaTriggerProgrammaticLaunchCompletion();
}

// ---------------------------------------------------------------------------
// Edge phase (R5-proven layout, LTS-capped ~41.6us at 512B/edge):
// out[e] = relu(A[src[e]] + B[dst[e]]) . W2 + b2
// ---------------------------------------------------------------------------
__device__ __forceinline__ float dot8(uint4 ua, uint4 ub,
                                      __half2 w0, __half2 w1,
                                      __half2 w2, __half2 w3, __half2 hz) {
    __half2 h0 = __hmax2(__hadd2(*(__half2*)&ua.x, *(__half2*)&ub.x), hz);
    __half2 h1 = __hmax2(__hadd2(*(__half2*)&ua.y, *(__half2*)&ub.y), hz);
    __half2 h2 = __hmax2(__hadd2(*(__half2*)&ua.z, *(__half2*)&ub.z), hz);
    __half2 h3 = __hmax2(__hadd2(*(__half2*)&ua.w, *(__half2*)&ub.w), hz);
    __half2 c1 = __hfma2(h1, w1, __hmul2(h0, w0));
    __half2 c2 = __hfma2(h3, w3, __hmul2(h2, w2));
    float2 f1 = __half22float2(c1);
    float2 f2 = __half22float2(c2);
    return (f1.x + f1.y) + (f2.x + f2.y);
}

__global__ __launch_bounds__(256)
void edge_kernel(const int* __restrict__ ei,
                 const float* __restrict__ W2,
                 const float* __restrict__ b2,
                 float* __restrict__ out,
                 int E)
{
    const int lane = threadIdx.x & 31;
    const int half = lane >> 4;
    const int q    = lane & 15;
    const int gw   = (blockIdx.x * blockDim.x + threadIdx.x) >> 5;
    const int nw   = (gridDim.x * blockDim.x) >> 5;

    // Prologue reads only harness inputs — safe before gridsync.
    float4 wlo = *(const float4*)&W2[q * 8];
    float4 whi = *(const float4*)&W2[q * 8 + 4];
    const __half2 w0 = __floats2half2_rn(wlo.x, wlo.y);
    const __half2 w1 = __floats2half2_rn(wlo.z, wlo.w);
    const __half2 w2 = __floats2half2_rn(whi.x, whi.y);
    const __half2 w3 = __floats2half2_rn(whi.z, whi.w);
    const float b2v = b2[0];
    const __half2 hz = __float2half2_rn(0.f);

    cudaGridDependencySynchronize();

    if ((E & 3) == 0) {
        for (int e0 = gw * 4; e0 < E; e0 += nw * 4) {
            int4 sq = *(const int4*)&ei[e0];
            int4 dq = *(const int4*)&ei[E + e0];
            int sA = half ? sq.y : sq.x;
            int dA = half ? dq.y : dq.x;
            int sB = half ? sq.w : sq.z;
            int dB = half ? dq.w : dq.z;

            uint4 a0  = *(const uint4*)&g_A[((size_t)sA << 7) + (q << 3)];
            uint4 bb0 = *(const uint4*)&g_B[((size_t)dA << 7) + (q << 3)];
            uint4 a1  = *(const uint4*)&g_A[((size_t)sB << 7) + (q << 3)];
            uint4 bb1 = *(const uint4*)&g_B[((size_t)dB << 7) + (q << 3)];

            float v0 = dot8(a0, bb0, w0, w1, w2, w3, hz);
            float v1 = dot8(a1, bb1, w0, w1, w2, w3, hz);

            #pragma unroll
            for (int off = 8; off > 0; off >>= 1) {
                v0 += __shfl_xor_sync(0xFFFFFFFFu, v0, off);
                v1 += __shfl_xor_sync(0xFFFFFFFFu, v1, off);
            }
            if (q == 0) {
                out[e0 + half]     = v0 + b2v;
                out[e0 + 2 + half] = v1 + b2v;
            }
        }
    } else {
        for (int e = gw; e < E; e += nw) {
            int s = ei[e], d = ei[E + e];
            uint2 ua = *(const uint2*)&g_A[(size_t)s * H + lane * 4];
            uint2 ub = *(const uint2*)&g_B[(size_t)d * H + lane * 4];
            __half2 h0 = __hmax2(__hadd2(*(__half2*)&ua.x, *(__half2*)&ub.x), hz);
            __half2 h1 = __hmax2(__hadd2(*(__half2*)&ua.y, *(__half2*)&ub.y), hz);
            float2 f0 = __half22float2(h0);
            float2 f1 = __half22float2(h1);
            float4 wv = *(const float4*)&W2[lane * 4];
            float v = f0.x * wv.x + f0.y * wv.y + f1.x * wv.z + f1.y * wv.w;
            #pragma unroll
            for (int off = 16; off > 0; off >>= 1)
                v += __shfl_xor_sync(0xFFFFFFFFu, v, off);
            if (lane == 0) out[e] = v + b2v;
        }
    }
}

// ---------------------------------------------------------------------------
extern "C" void kernel_launch(void* const* d_in, const int* in_sizes, int n_in,
                              void* d_out, int out_size)
{
    const float* user  = (const float*)d_in[0];
    const float* movie = (const float*)d_in[1];
    const int*   ei    = (const int*)d_in[2];
    const float* W1    = (const float*)d_in[3];
    const float* b1    = (const float*)d_in[4];
    const float* W2    = (const float*)d_in[5];
    const float* b2    = (const float*)d_in[6];
    float* out = (float*)d_out;

    int n_users  = in_sizes[0] / H;
    int n_movies = in_sizes[1] / H;
    int E        = in_sizes[2] / 2;
    if (n_users  > MAX_ROWS) n_users  = MAX_ROWS;
    if (n_movies > MAX_ROWS) n_movies = MAX_ROWS;

    const int blocksA = (n_users  + BM - 1) / BM;
    const int blocksB = (n_movies + BM - 1) / BM;

    const int smem_bytes = (BM + H) * LDH * (int)sizeof(__half);  // 68 KB
    static bool attr_set = false;
    if (!attr_set) {
        cudaFuncSetAttribute(precompute_fp16,
                             cudaFuncAttributeMaxDynamicSharedMemorySize,
                             smem_bytes);
        attr_set = true;
    }

    // 1) W1 -> fp16 (fires PDL trigger early)
    convert_W_kernel<<<32, 256>>>(W1);

    cudaLaunchAttribute pdl[1];
    pdl[0].id = cudaLaunchAttributeProgrammaticStreamSerialization;
    pdl[0].val.programmaticStreamSerializationAllowed = 1;

    // 2) A/B tables — PDL: overlaps with convert, gridsyncs before W read.
    {
        cudaLaunchConfig_t cfg = {};
        cfg.gridDim = dim3((unsigned)(blocksA + blocksB), 1, 1);
        cfg.blockDim = dim3(256, 1, 1);
        cfg.dynamicSmemBytes = (size_t)smem_bytes;
        cfg.stream = 0;
        cfg.attrs = pdl;
        cfg.numAttrs = 1;
        cudaLaunchKernelEx(&cfg, precompute_fp16,
                           user, movie, b1, n_users, n_movies, blocksA);
    }
    // 3) Edge scoring — PDL: ramps under precompute tail.
    {
        cudaLaunchConfig_t cfg = {};
        cfg.gridDim = dim3(148 * 8, 1, 1);
        cfg.blockDim = dim3(256, 1, 1);
        cfg.dynamicSmemBytes = 0;
        cfg.stream = 0;
        cfg.attrs = pdl;
        cfg.numAttrs = 1;
        cudaLaunchKernelEx(&cfg, edge_kernel, ei, W2, b2, out, E);
    }
}